// round 14
// baseline (speedup 1.0000x reference)
#include <cuda_runtime.h>
#include <math.h>

// Accumulators: 0 cls_sum, 1 npos, 2 bbox_sum, 3 nfg, 4 iou_sum, 5 num_sum, 6 nmask
__device__ double g_acc[7];
// Spatial bucketing of anchors into 16x16 cells of 64px over (cx, cy).
#define NCELL 256
__device__ int g_hist[NCELL];
__device__ int g_cursor[NCELL];
__device__ int g_perm[131072];

#define CHUNK 2048

__global__ void k_zero() {
    const int t = threadIdx.x;
    if (t < NCELL) g_hist[t] = 0;
    if (t < 7) g_acc[t] = 0.0;
}

__device__ __forceinline__ int cell_of(const float4 anc) {
    const float cx = anc.x + 0.5f * (anc.z - anc.x);
    const float cy = anc.y + 0.5f * (anc.w - anc.y);
    int ix = (int)(cx * 0.015625f);  // /64
    int iy = (int)(cy * 0.015625f);
    ix = min(15, max(0, ix));
    iy = min(15, max(0, iy));
    return iy * 16 + ix;
}

// Privatized histogram: smem counts, one aggregated global atomic per (block, cell).
__global__ void k_hist(const float* __restrict__ anchors, int A) {
    __shared__ int h[NCELL];
    for (int i = threadIdx.x; i < NCELL; i += blockDim.x) h[i] = 0;
    __syncthreads();
    const int end = min(A, (int)(blockIdx.x * CHUNK + CHUNK));
    for (int a = blockIdx.x * CHUNK + threadIdx.x; a < end; a += blockDim.x) {
        const float4 anc = __ldg((const float4*)anchors + a);
        atomicAdd(&h[cell_of(anc)], 1);
    }
    __syncthreads();
    for (int i = threadIdx.x; i < NCELL; i += blockDim.x)
        if (h[i]) atomicAdd(&g_hist[i], h[i]);
}

__global__ void k_scan() {  // 256 threads, exclusive scan -> g_cursor
    const int t = threadIdx.x;
    int v = g_hist[t];
    const int orig = v;
    #pragma unroll
    for (int d = 1; d < 32; d <<= 1) {
        int n = __shfl_up_sync(0xffffffffu, v, d);
        if ((t & 31) >= d) v += n;
    }
    __shared__ int wsum[8];
    if ((t & 31) == 31) wsum[t >> 5] = v;
    __syncthreads();
    if (t < 8) {
        int w = wsum[t];
        #pragma unroll
        for (int d = 1; d < 8; d <<= 1) {
            int n = __shfl_up_sync(0xffu, w, d);
            if (t >= d) w += n;
        }
        wsum[t] = w;
    }
    __syncthreads();
    const int base = v - orig + ((t >= 32) ? wsum[(t >> 5) - 1] : 0);
    g_cursor[t] = base;
}

// Privatized scatter: block reserves a contiguous range per cell with one
// global atomic, then places its anchors via smem cursors.
__global__ void k_scatter(const float* __restrict__ anchors, int A) {
    __shared__ int h[NCELL];
    __shared__ int basev[NCELL];
    for (int i = threadIdx.x; i < NCELL; i += blockDim.x) h[i] = 0;
    __syncthreads();
    const int end = min(A, (int)(blockIdx.x * CHUNK + CHUNK));
    for (int a = blockIdx.x * CHUNK + threadIdx.x; a < end; a += blockDim.x) {
        const float4 anc = __ldg((const float4*)anchors + a);
        atomicAdd(&h[cell_of(anc)], 1);
    }
    __syncthreads();
    for (int i = threadIdx.x; i < NCELL; i += blockDim.x) {
        basev[i] = h[i] ? atomicAdd(&g_cursor[i], h[i]) : 0;
    }
    __syncthreads();
    for (int i = threadIdx.x; i < NCELL; i += blockDim.x) h[i] = 0;
    __syncthreads();
    for (int a = blockIdx.x * CHUNK + threadIdx.x; a < end; a += blockDim.x) {
        const float4 anc = __ldg((const float4*)anchors + a);
        const int c = cell_of(anc);
        const int off = atomicAdd(&h[c], 1);
        g_perm[basev[c] + off] = a;
    }
}

// IoU with pre-added +1 on x1/y1 of both boxes, SINGLE clamp (may return <= 0
// for disjoint boxes; sorts below every true overlap under signed compare).
__device__ __forceinline__ float iou1c(float bx0, float by0, float bx1p, float by1p, float ab,
                                       float gx0, float gy0, float gx1p, float gy1p, float ag) {
    float iw = fminf(bx1p, gx1p) - fmaxf(bx0, gx0);
    float ih = fminf(by1p, gy1p) - fmaxf(by0, gy0);
    float inter = fmaxf(iw, 0.0f) * ih;
    float uni = (ab + ag) - inter;
    return __fdividef(inter, uni);
}

__device__ __forceinline__ float sl1(float x) {
    float ax = fabsf(x);
    return (ax < (1.0f / 9.0f)) ? 4.5f * x * x : (ax - (float)(0.5 / 9.0));
}

#define IDX_MASK 0x1FF
#define VAL_MASK 0xFFFFFE00u

__global__ __launch_bounds__(128, 8) void k_main(
    const float* __restrict__ pred_cls,
    const float* __restrict__ rpn_num_prob,
    const float* __restrict__ pred_reg,
    const float* __restrict__ anchors,
    const float* __restrict__ rpn_iou,
    const float* __restrict__ boxes,
    int A, int G)
{
    extern __shared__ float sm[];
    float4* sA  = (float4*)sm;             // valid gts (gx0, gy0, gx1+1, gy1+1)
    float4* sB  = (float4*)(sm + 4 * G);   // block-filtered gts
    float*  sAr = sm + 8 * G;              // valid gt areas
    float*  sBr = sm + 9 * G;              // filtered gt areas
    __shared__ int s_wcnt[4];
    __shared__ int s_woff[4];
    __shared__ int s_cnt;
    __shared__ float4 s_wbb[4];
    __shared__ float4 s_bb;

    const int tid = threadIdx.x;
    const int wid = tid >> 5;
    const int lane = tid & 31;
    const int img = blockIdx.y;
    const float* gtb = boxes + (size_t)img * G * 5;

    // ---- stable compaction of valid gt boxes into shared memory ----
    if (tid == 0) s_cnt = 0;
    __syncthreads();
    for (int jb = 0; jb < G; jb += blockDim.x) {
        const int j = jb + tid;
        bool valid = false;
        float x0 = 0.f, y0 = 0.f, x1 = 0.f, y1 = 0.f;
        if (j < G) {
            x0 = gtb[j * 5 + 0];
            y0 = gtb[j * 5 + 1];
            x1 = gtb[j * 5 + 2];
            y1 = gtb[j * 5 + 3];
            valid = (gtb[j * 5 + 4] != -1.0f);
        }
        const unsigned m = __ballot_sync(0xffffffffu, valid);
        if (lane == 0) s_wcnt[wid] = __popc(m);
        __syncthreads();
        if (tid == 0) {
            int s = s_cnt;
            #pragma unroll
            for (int w = 0; w < 4; w++) { s_woff[w] = s; s += s_wcnt[w]; }
            s_cnt = s;
        }
        __syncthreads();
        if (valid) {
            const int pos = s_woff[wid] + __popc(m & ((1u << lane) - 1u));
            sA[pos] = make_float4(x0, y0, x1 + 1.0f, y1 + 1.0f);
            sAr[pos] = (x1 - x0 + 1.0f) * (y1 - y0 + 1.0f);
        }
        __syncthreads();
    }
    const int Gv = s_cnt;

    float cls_s = 0.f, npos = 0.f, bb_s = 0.f, nfg = 0.f, iou_s = 0.f, num_s = 0.f, nmask = 0.f;

    const int idx = blockIdx.x * blockDim.x + tid;
    const bool va = (idx < A);
    const int a = va ? g_perm[idx] : g_perm[0];

    const float4 anc = __ldg((const float4*)anchors + a);
    const float aw = anc.z - anc.x + 1.0f;
    const float ah = anc.w - anc.y + 1.0f;
    const float acx = anc.x + 0.5f * aw;
    const float acy = anc.y + 0.5f * ah;
    const float area_a = aw * ah;
    const float ax1p = anc.z + 1.0f;
    const float ay1p = anc.w + 1.0f;

    const size_t base = (size_t)img * A + a;
    const float4* pr = (const float4*)pred_reg + base * 2;
    const float CLIP = 4.135166556742356f;  // log(1000/16)

    float e0x0, e0y0, e0x1p, e0y1p, area0;
    float e1x0, e1y0, e1x1p, e1y1p, area1;
    {
        const float4 d0 = __ldg(pr);
        const float4 d1 = __ldg(pr + 1);
        float pcx = acx + d0.x * aw;
        float pcy = acy + d0.y * ah;
        float pw = aw * expf(fminf(d0.z, CLIP));
        float ph = ah * expf(fminf(d0.w, CLIP));
        e0x0 = pcx - 0.5f * pw; e0y0 = pcy - 0.5f * ph;
        e0x1p = pcx + 0.5f * pw + 1.0f; e0y1p = pcy + 0.5f * ph + 1.0f;
        area0 = (e0x1p - e0x0) * (e0y1p - e0y0);
        pcx = acx + d1.x * aw;
        pcy = acy + d1.y * ah;
        pw = aw * expf(fminf(d1.z, CLIP));
        ph = ah * expf(fminf(d1.w, CLIP));
        e1x0 = pcx - 0.5f * pw; e1y0 = pcy - 0.5f * ph;
        e1x1p = pcx + 0.5f * pw + 1.0f; e1y1p = pcy + 0.5f * ph + 1.0f;
        area1 = (e1x1p - e1x0) * (e1y1p - e1y0);
    }
    // per-thread union (bounding) box of anchor + both decoded boxes
    const float px0  = fminf(anc.x, fminf(e0x0, e1x0));
    const float py0  = fminf(anc.y, fminf(e0y0, e1y0));
    const float px1p = fmaxf(ax1p, fmaxf(e0x1p, e1x1p));
    const float py1p = fmaxf(ay1p, fmaxf(e0y1p, e1y1p));

    // ---- block-level bbox (spatial sort makes this tight: ~one 64px cell) ----
    {
        float bx0 = px0, by0 = py0, bx1 = px1p, by1 = py1p;
        #pragma unroll
        for (int d = 16; d; d >>= 1) {
            bx0 = fminf(bx0, __shfl_xor_sync(0xffffffffu, bx0, d));
            by0 = fminf(by0, __shfl_xor_sync(0xffffffffu, by0, d));
            bx1 = fmaxf(bx1, __shfl_xor_sync(0xffffffffu, bx1, d));
            by1 = fmaxf(by1, __shfl_xor_sync(0xffffffffu, by1, d));
        }
        if (lane == 0) s_wbb[wid] = make_float4(bx0, by0, bx1, by1);
        __syncthreads();
        if (tid == 0) {
            float4 r = s_wbb[0];
            #pragma unroll
            for (int w = 1; w < 4; w++) {
                r.x = fminf(r.x, s_wbb[w].x);
                r.y = fminf(r.y, s_wbb[w].y);
                r.z = fmaxf(r.z, s_wbb[w].z);
                r.w = fmaxf(r.w, s_wbb[w].w);
            }
            s_bb = r;
            s_cnt = 0;
        }
        __syncthreads();
    }
    const float4 bb = s_bb;

    // ---- stable compaction of gts intersecting the block bbox ----
    for (int jb = 0; jb < Gv; jb += blockDim.x) {
        const int j = jb + tid;
        bool keep = false;
        float4 g;
        if (j < Gv) {
            g = sA[j];
            keep = (bb.z > g.x) & (g.z > bb.x) & (bb.w > g.y) & (g.w > bb.y);
        }
        const unsigned m = __ballot_sync(0xffffffffu, keep);
        if (lane == 0) s_wcnt[wid] = __popc(m);
        __syncthreads();
        if (tid == 0) {
            int s = s_cnt;
            #pragma unroll
            for (int w = 0; w < 4; w++) { s_woff[w] = s; s += s_wcnt[w]; }
            s_cnt = s;
        }
        __syncthreads();
        if (keep) {
            const int pos = s_woff[wid] + __popc(m & ((1u << lane) - 1u));
            sB[pos] = g;
            sBr[pos] = sAr[j];
        }
        __syncthreads();
    }
    const int Gc = s_cnt;

    // anchor top-2: exact branchy tracker (indices into sB)
    float v1a = -1e30f, v2a = -1e30f; int i1a = 0, i2a = 0;
    // dt0 argmax + dt1 top-2: packed SIGNED trackers (stable compaction keeps
    // sB order monotone in original order -> tie-break identical)
    int pa = 0, pb1 = 0, pb2 = 0;
    int u = 511;  // u = 511 - j (sB index)

    #pragma unroll 1
    for (int j = 0; j < Gc; ++j, --u) {
        const float4 g = sB[j];
        const bool hit = (px1p > g.x) & (g.z > px0) & (py1p > g.y) & (g.w > py0);
        if (__any_sync(0xffffffffu, hit)) {
            const float ag = sBr[j];

            const float ioa = iou1c(anc.x, anc.y, ax1p, ay1p, area_a, g.x, g.y, g.z, g.w, ag);
            if (ioa > v1a)      { v2a = v1a; i2a = i1a; v1a = ioa; i1a = j; }
            else if (ioa > v2a) { v2a = ioa; i2a = j; }

            const float io0 = iou1c(e0x0, e0y0, e0x1p, e0y1p, area0, g.x, g.y, g.z, g.w, ag);
            const int e0 = (int)((__float_as_uint(io0) & VAL_MASK) | (unsigned)u);
            pa = max(pa, e0);

            const float io1 = iou1c(e1x0, e1y0, e1x1p, e1y1p, area1, g.x, g.y, g.z, g.w, ag);
            const int e1 = (int)((__float_as_uint(io1) & VAL_MASK) | (unsigned)u);
            pb2 = max(pb2, min(pb1, e1));
            pb1 = max(pb1, e1);
        }
    }

    if (va) {
        const int ai = 511 - (pa & IDX_MASK);
        const float am = fmaxf(__uint_as_float((unsigned)pa & VAL_MASK), 0.0f);
        const int bi = 511 - (pb1 & IDX_MASK);
        const float bm1 = fmaxf(__uint_as_float((unsigned)pb1 & VAL_MASK), 0.0f);
        const float bm2 = fmaxf(__uint_as_float((unsigned)pb2 & VAL_MASK), 0.0f);

        const float la = (v1a >= 0.5f) ? 1.0f : ((v1a < 0.4f) ? 0.0f : -1.0f);
        const float lb = (v2a >= 0.5f) ? 1.0f : ((v2a < 0.4f) ? 0.0f : -1.0f);
        const float ign = (la == 0.0f && lb != 0.0f) ? (lb - 1.0f) : lb;

        const float2 pc = __ldg((const float2*)pred_cls + base);
        if (la != -1.0f) {
            cls_s += (la == 1.0f)
                   ? (-0.25f * (1.0f - pc.x) * (1.0f - pc.x) * logf(pc.x))
                   : (-0.75f * pc.x * pc.x * logf(1.0f - pc.x));
        }
        if (ign != -1.0f) {
            cls_s += (ign == 1.0f)
                   ? (-0.25f * (1.0f - pc.y) * (1.0f - pc.y) * logf(pc.y))
                   : (-0.75f * pc.y * pc.y * logf(1.0f - pc.y));
        }
        npos += (la == 1.0f) ? 1.0f : 0.0f;
        npos += (ign == 1.0f) ? 1.0f : 0.0f;

        const bool fg0 = (la == 1.0f);
        const bool fg1 = (ign == 1.0f) || (ign == -2.0f);

        const float2 qi = __ldg((const float2*)rpn_iou + base);
        const float bval = (bi == ai) ? bm2 : bm1;

        if (fg0 || fg1) {
            const float4 rd0 = __ldg(pr);
            const float4 rd1 = __ldg(pr + 1);
            if (fg0) {
                const float4 g = sB[i1a];
                const float gw = g.z - g.x;
                const float gh = g.w - g.y;
                const float gcx = g.x + 0.5f * gw;
                const float gcy = g.y + 0.5f * gh;
                const float t0 = (gcx - acx) / aw;
                const float t1 = (gcy - acy) / ah;
                const float t2 = logf(gw / aw);
                const float t3 = logf(gh / ah);
                bb_s += sl1(rd0.x - t0) + sl1(rd0.y - t1) + sl1(rd0.z - t2) + sl1(rd0.w - t3);
                nfg += 1.0f;
                iou_s += fabsf(qi.x - am);
            }
            if (fg1) {
                const float4 g = sB[i2a];
                const float gw = g.z - g.x;
                const float gh = g.w - g.y;
                const float gcx = g.x + 0.5f * gw;
                const float gcy = g.y + 0.5f * gh;
                const float t0 = (gcx - acx) / aw;
                const float t1 = (gcy - acy) / ah;
                const float t2 = logf(gw / aw);
                const float t3 = logf(gh / ah);
                bb_s += sl1(rd1.x - t0) + sl1(rd1.y - t1) + sl1(rd1.z - t2) + sl1(rd1.w - t3);
                nfg += 1.0f;
                iou_s += fabsf(qi.y - bval);
            }
        }

        const int nl = ((la == 1.0f) ? 1 : 0) + ((ign == 1.0f) ? 1 : 0) - 1;
        if (nl >= 0) {
            const float2 sc = __ldg((const float2*)rpn_num_prob + base);
            const float mx = fmaxf(sc.x, sc.y);
            const float lse = mx + logf(expf(sc.x - mx) + expf(sc.y - mx));
            num_s += lse - ((nl == 0) ? sc.x : sc.y);
            nmask += 1.0f;
        }
    }

    // block reduction: warp shfl -> shared -> one double atomic per block per acc
    float vals[7] = {cls_s, npos, bb_s, nfg, iou_s, num_s, nmask};
    #pragma unroll
    for (int k = 0; k < 7; k++) {
        float v = vals[k];
        v += __shfl_down_sync(0xffffffffu, v, 16);
        v += __shfl_down_sync(0xffffffffu, v, 8);
        v += __shfl_down_sync(0xffffffffu, v, 4);
        v += __shfl_down_sync(0xffffffffu, v, 2);
        v += __shfl_down_sync(0xffffffffu, v, 1);
        vals[k] = v;
    }
    __shared__ float red[4][7];
    if (lane == 0) {
        #pragma unroll
        for (int k = 0; k < 7; k++) red[wid][k] = vals[k];
    }
    __syncthreads();
    if (tid < 7) {
        float s = red[0][tid] + red[1][tid] + red[2][tid] + red[3][tid];
        atomicAdd(&g_acc[tid], (double)s);
    }
}

__global__ void k_final(float* out) {
    if (threadIdx.x == 0) {
        const double npos = (g_acc[1] > 1.0) ? g_acc[1] : 1.0;
        const double nfg  = (g_acc[3] > 1.0) ? g_acc[3] : 1.0;
        const double nm   = (g_acc[6] > 1.0) ? g_acc[6] : 1.0;
        out[0] = (float)(g_acc[0] / npos);
        out[1] = (float)(2.0 * g_acc[2] / nfg);
        out[2] = (float)(2.0 * g_acc[4] / nfg);
        out[3] = (float)(g_acc[5] / nm);
    }
}

extern "C" void kernel_launch(void* const* d_in, const int* in_sizes, int n_in,
                              void* d_out, int out_size) {
    const float* pred_cls     = (const float*)d_in[0];
    const float* rpn_num_prob = (const float*)d_in[1];
    const float* pred_reg     = (const float*)d_in[2];
    const float* anchors      = (const float*)d_in[3];
    const float* rpn_iou      = (const float*)d_in[4];
    const float* boxes        = (const float*)d_in[5];
    // d_in[6] = im_info (unused; G and n recovered from sizes)

    const int A = in_sizes[3] / 4;
    const int n = in_sizes[0] / (2 * A);
    const int G = in_sizes[5] / (5 * n);

    k_zero<<<1, 256>>>();
    k_hist<<<(A + CHUNK - 1) / CHUNK, 256>>>(anchors, A);
    k_scan<<<1, 256>>>();
    k_scatter<<<(A + CHUNK - 1) / CHUNK, 256>>>(anchors, A);

    dim3 grid((A + 127) / 128, n);
    const size_t smem = (size_t)10 * G * sizeof(float);
    k_main<<<grid, 128, smem>>>(pred_cls, rpn_num_prob, pred_reg, anchors,
                                rpn_iou, boxes, A, G);
    k_final<<<1, 32>>>((float*)d_out);
}

// round 15
// speedup vs baseline: 1.4847x; 1.4847x over previous
#include <cuda_runtime.h>
#include <math.h>

// Accumulators: 0 cls_sum, 1 npos, 2 bbox_sum, 3 nfg, 4 iou_sum, 5 num_sum, 6 nmask
__device__ double g_acc[7];
// Spatial bucketing of anchors into 16x16 cells of 64px over (cx, cy).
#define NCELL 256
#define CHUNK 8192
#define MAXB 64
__device__ int g_hist[NCELL];
__device__ int g_cursor[NCELL];
__device__ int g_bhist[MAXB][NCELL];
__device__ int g_perm[131072];

__global__ void k_zero() {
    const int t = threadIdx.x;
    if (t < NCELL) g_hist[t] = 0;
    if (t < 7) g_acc[t] = 0.0;
}

__device__ __forceinline__ int cell_of(const float4 anc) {
    const float cx = anc.x + 0.5f * (anc.z - anc.x);
    const float cy = anc.y + 0.5f * (anc.w - anc.y);
    int ix = (int)(cx * 0.015625f);  // /64
    int iy = (int)(cy * 0.015625f);
    ix = min(15, max(0, ix));
    iy = min(15, max(0, iy));
    return iy * 16 + ix;
}

// Privatized histogram: smem counts; persists per-block counts for k_scatter
// and aggregates into the global histogram.
__global__ void k_hist(const float* __restrict__ anchors, int A) {
    __shared__ int h[NCELL];
    for (int i = threadIdx.x; i < NCELL; i += blockDim.x) h[i] = 0;
    __syncthreads();
    const int end = min(A, (int)(blockIdx.x * CHUNK + CHUNK));
    for (int a = blockIdx.x * CHUNK + threadIdx.x; a < end; a += blockDim.x) {
        const float4 anc = __ldg((const float4*)anchors + a);
        atomicAdd(&h[cell_of(anc)], 1);
    }
    __syncthreads();
    for (int i = threadIdx.x; i < NCELL; i += blockDim.x) {
        g_bhist[blockIdx.x][i] = h[i];
        if (h[i]) atomicAdd(&g_hist[i], h[i]);
    }
}

__global__ void k_scan() {  // 256 threads, exclusive scan -> g_cursor
    const int t = threadIdx.x;
    int v = g_hist[t];
    const int orig = v;
    #pragma unroll
    for (int d = 1; d < 32; d <<= 1) {
        int n = __shfl_up_sync(0xffffffffu, v, d);
        if ((t & 31) >= d) v += n;
    }
    __shared__ int wsum[8];
    if ((t & 31) == 31) wsum[t >> 5] = v;
    __syncthreads();
    if (t < 8) {
        int w = wsum[t];
        #pragma unroll
        for (int d = 1; d < 8; d <<= 1) {
            int n = __shfl_up_sync(0xffu, w, d);
            if (t >= d) w += n;
        }
        wsum[t] = w;
    }
    __syncthreads();
    const int base = v - orig + ((t >= 32) ? wsum[(t >> 5) - 1] : 0);
    g_cursor[t] = base;
}

// Scatter reusing k_hist's per-block counts: reserve contiguous ranges per
// cell with one global atomic each, then place anchors via smem cursors.
__global__ void k_scatter(const float* __restrict__ anchors, int A) {
    __shared__ int h[NCELL];
    __shared__ int basev[NCELL];
    for (int i = threadIdx.x; i < NCELL; i += blockDim.x) {
        const int bh = g_bhist[blockIdx.x][i];
        basev[i] = bh ? atomicAdd(&g_cursor[i], bh) : 0;
        h[i] = 0;
    }
    __syncthreads();
    const int end = min(A, (int)(blockIdx.x * CHUNK + CHUNK));
    for (int a = blockIdx.x * CHUNK + threadIdx.x; a < end; a += blockDim.x) {
        const float4 anc = __ldg((const float4*)anchors + a);
        const int c = cell_of(anc);
        const int off = atomicAdd(&h[c], 1);
        g_perm[basev[c] + off] = a;
    }
}

// IoU with pre-added +1 on x1/y1 of both boxes, SINGLE clamp (may return <= 0
// for disjoint boxes; sorts below every true overlap under signed compare).
__device__ __forceinline__ float iou1c(float bx0, float by0, float bx1p, float by1p, float ab,
                                       float gx0, float gy0, float gx1p, float gy1p, float ag) {
    float iw = fminf(bx1p, gx1p) - fmaxf(bx0, gx0);
    float ih = fminf(by1p, gy1p) - fmaxf(by0, gy0);
    float inter = fmaxf(iw, 0.0f) * ih;
    float uni = (ab + ag) - inter;
    return __fdividef(inter, uni);
}

__device__ __forceinline__ float sl1(float x) {
    float ax = fabsf(x);
    return (ax < (1.0f / 9.0f)) ? 4.5f * x * x : (ax - (float)(0.5 / 9.0));
}

#define IDX_MASK 0x1FF
#define VAL_MASK 0xFFFFFE00u

__global__ __launch_bounds__(128, 8) void k_main(
    const float* __restrict__ pred_cls,
    const float* __restrict__ rpn_num_prob,
    const float* __restrict__ pred_reg,
    const float* __restrict__ anchors,
    const float* __restrict__ rpn_iou,
    const float* __restrict__ boxes,
    int A, int G)
{
    extern __shared__ float sm[];
    float4* sA  = (float4*)sm;             // valid gts (gx0, gy0, gx1+1, gy1+1)
    float4* sB  = (float4*)(sm + 4 * G);   // block-filtered gts
    float*  sAr = sm + 8 * G;              // valid gt areas
    float*  sBr = sm + 9 * G;              // filtered gt areas
    __shared__ int s_wcnt[4];
    __shared__ int s_woff[4];
    __shared__ int s_cnt;
    __shared__ float4 s_wbb[4];
    __shared__ float4 s_bb;

    const int tid = threadIdx.x;
    const int wid = tid >> 5;
    const int lane = tid & 31;
    const int img = blockIdx.y;
    const float* gtb = boxes + (size_t)img * G * 5;

    // ---- stable compaction of valid gt boxes into shared memory ----
    if (tid == 0) s_cnt = 0;
    __syncthreads();
    for (int jb = 0; jb < G; jb += blockDim.x) {
        const int j = jb + tid;
        bool valid = false;
        float x0 = 0.f, y0 = 0.f, x1 = 0.f, y1 = 0.f;
        if (j < G) {
            x0 = gtb[j * 5 + 0];
            y0 = gtb[j * 5 + 1];
            x1 = gtb[j * 5 + 2];
            y1 = gtb[j * 5 + 3];
            valid = (gtb[j * 5 + 4] != -1.0f);
        }
        const unsigned m = __ballot_sync(0xffffffffu, valid);
        if (lane == 0) s_wcnt[wid] = __popc(m);
        __syncthreads();
        if (tid == 0) {
            int s = s_cnt;
            #pragma unroll
            for (int w = 0; w < 4; w++) { s_woff[w] = s; s += s_wcnt[w]; }
            s_cnt = s;
        }
        __syncthreads();
        if (valid) {
            const int pos = s_woff[wid] + __popc(m & ((1u << lane) - 1u));
            sA[pos] = make_float4(x0, y0, x1 + 1.0f, y1 + 1.0f);
            sAr[pos] = (x1 - x0 + 1.0f) * (y1 - y0 + 1.0f);
        }
        __syncthreads();
    }
    const int Gv = s_cnt;

    float cls_s = 0.f, npos = 0.f, bb_s = 0.f, nfg = 0.f, iou_s = 0.f, num_s = 0.f, nmask = 0.f;

    const int idx = blockIdx.x * blockDim.x + tid;
    const bool va = (idx < A);
    const int a = va ? g_perm[idx] : g_perm[0];

    const float4 anc = __ldg((const float4*)anchors + a);
    const float aw = anc.z - anc.x + 1.0f;
    const float ah = anc.w - anc.y + 1.0f;
    const float acx = anc.x + 0.5f * aw;
    const float acy = anc.y + 0.5f * ah;
    const float area_a = aw * ah;
    const float ax1p = anc.z + 1.0f;
    const float ay1p = anc.w + 1.0f;

    const size_t base = (size_t)img * A + a;
    const float4* pr = (const float4*)pred_reg + base * 2;
    const float CLIP = 4.135166556742356f;  // log(1000/16)

    float e0x0, e0y0, e0x1p, e0y1p, area0;
    float e1x0, e1y0, e1x1p, e1y1p, area1;
    {
        const float4 d0 = __ldg(pr);
        const float4 d1 = __ldg(pr + 1);
        float pcx = acx + d0.x * aw;
        float pcy = acy + d0.y * ah;
        float pw = aw * expf(fminf(d0.z, CLIP));
        float ph = ah * expf(fminf(d0.w, CLIP));
        e0x0 = pcx - 0.5f * pw; e0y0 = pcy - 0.5f * ph;
        e0x1p = pcx + 0.5f * pw + 1.0f; e0y1p = pcy + 0.5f * ph + 1.0f;
        area0 = (e0x1p - e0x0) * (e0y1p - e0y0);
        pcx = acx + d1.x * aw;
        pcy = acy + d1.y * ah;
        pw = aw * expf(fminf(d1.z, CLIP));
        ph = ah * expf(fminf(d1.w, CLIP));
        e1x0 = pcx - 0.5f * pw; e1y0 = pcy - 0.5f * ph;
        e1x1p = pcx + 0.5f * pw + 1.0f; e1y1p = pcy + 0.5f * ph + 1.0f;
        area1 = (e1x1p - e1x0) * (e1y1p - e1y0);
    }
    // per-thread union (bounding) box of anchor + both decoded boxes
    const float px0  = fminf(anc.x, fminf(e0x0, e1x0));
    const float py0  = fminf(anc.y, fminf(e0y0, e1y0));
    const float px1p = fmaxf(ax1p, fmaxf(e0x1p, e1x1p));
    const float py1p = fmaxf(ay1p, fmaxf(e0y1p, e1y1p));

    // ---- block-level bbox (spatial sort makes this tight: ~one 64px cell) ----
    {
        float bx0 = px0, by0 = py0, bx1 = px1p, by1 = py1p;
        #pragma unroll
        for (int d = 16; d; d >>= 1) {
            bx0 = fminf(bx0, __shfl_xor_sync(0xffffffffu, bx0, d));
            by0 = fminf(by0, __shfl_xor_sync(0xffffffffu, by0, d));
            bx1 = fmaxf(bx1, __shfl_xor_sync(0xffffffffu, bx1, d));
            by1 = fmaxf(by1, __shfl_xor_sync(0xffffffffu, by1, d));
        }
        if (lane == 0) s_wbb[wid] = make_float4(bx0, by0, bx1, by1);
        __syncthreads();
        if (tid == 0) {
            float4 r = s_wbb[0];
            #pragma unroll
            for (int w = 1; w < 4; w++) {
                r.x = fminf(r.x, s_wbb[w].x);
                r.y = fminf(r.y, s_wbb[w].y);
                r.z = fmaxf(r.z, s_wbb[w].z);
                r.w = fmaxf(r.w, s_wbb[w].w);
            }
            s_bb = r;
            s_cnt = 0;
        }
        __syncthreads();
    }
    const float4 bb = s_bb;

    // ---- stable compaction of gts intersecting the block bbox ----
    for (int jb = 0; jb < Gv; jb += blockDim.x) {
        const int j = jb + tid;
        bool keep = false;
        float4 g;
        if (j < Gv) {
            g = sA[j];
            keep = (bb.z > g.x) & (g.z > bb.x) & (bb.w > g.y) & (g.w > bb.y);
        }
        const unsigned m = __ballot_sync(0xffffffffu, keep);
        if (lane == 0) s_wcnt[wid] = __popc(m);
        __syncthreads();
        if (tid == 0) {
            int s = s_cnt;
            #pragma unroll
            for (int w = 0; w < 4; w++) { s_woff[w] = s; s += s_wcnt[w]; }
            s_cnt = s;
        }
        __syncthreads();
        if (keep) {
            const int pos = s_woff[wid] + __popc(m & ((1u << lane) - 1u));
            sB[pos] = g;
            sBr[pos] = sAr[j];
        }
        __syncthreads();
    }
    const int Gc = s_cnt;

    // anchor top-2: exact branchy tracker (indices into sB)
    float v1a = -1e30f, v2a = -1e30f; int i1a = 0, i2a = 0;
    // dt0 argmax + dt1 top-2: packed SIGNED trackers (stable compaction keeps
    // sB order monotone in original order -> tie-break identical)
    int pa = 0, pb1 = 0, pb2 = 0;
    int u = 511;  // u = 511 - j (sB index)

    #pragma unroll 1
    for (int j = 0; j < Gc; ++j, --u) {
        const float4 g = sB[j];
        const bool hit = (px1p > g.x) & (g.z > px0) & (py1p > g.y) & (g.w > py0);
        if (__any_sync(0xffffffffu, hit)) {
            const float ag = sBr[j];

            const float ioa = iou1c(anc.x, anc.y, ax1p, ay1p, area_a, g.x, g.y, g.z, g.w, ag);
            if (ioa > v1a)      { v2a = v1a; i2a = i1a; v1a = ioa; i1a = j; }
            else if (ioa > v2a) { v2a = ioa; i2a = j; }

            const float io0 = iou1c(e0x0, e0y0, e0x1p, e0y1p, area0, g.x, g.y, g.z, g.w, ag);
            const int e0 = (int)((__float_as_uint(io0) & VAL_MASK) | (unsigned)u);
            pa = max(pa, e0);

            const float io1 = iou1c(e1x0, e1y0, e1x1p, e1y1p, area1, g.x, g.y, g.z, g.w, ag);
            const int e1 = (int)((__float_as_uint(io1) & VAL_MASK) | (unsigned)u);
            pb2 = max(pb2, min(pb1, e1));
            pb1 = max(pb1, e1);
        }
    }

    if (va) {
        const int ai = 511 - (pa & IDX_MASK);
        const float am = fmaxf(__uint_as_float((unsigned)pa & VAL_MASK), 0.0f);
        const int bi = 511 - (pb1 & IDX_MASK);
        const float bm1 = fmaxf(__uint_as_float((unsigned)pb1 & VAL_MASK), 0.0f);
        const float bm2 = fmaxf(__uint_as_float((unsigned)pb2 & VAL_MASK), 0.0f);

        const float la = (v1a >= 0.5f) ? 1.0f : ((v1a < 0.4f) ? 0.0f : -1.0f);
        const float lb = (v2a >= 0.5f) ? 1.0f : ((v2a < 0.4f) ? 0.0f : -1.0f);
        const float ign = (la == 0.0f && lb != 0.0f) ? (lb - 1.0f) : lb;

        const float2 pc = __ldg((const float2*)pred_cls + base);
        if (la != -1.0f) {
            cls_s += (la == 1.0f)
                   ? (-0.25f * (1.0f - pc.x) * (1.0f - pc.x) * logf(pc.x))
                   : (-0.75f * pc.x * pc.x * logf(1.0f - pc.x));
        }
        if (ign != -1.0f) {
            cls_s += (ign == 1.0f)
                   ? (-0.25f * (1.0f - pc.y) * (1.0f - pc.y) * logf(pc.y))
                   : (-0.75f * pc.y * pc.y * logf(1.0f - pc.y));
        }
        npos += (la == 1.0f) ? 1.0f : 0.0f;
        npos += (ign == 1.0f) ? 1.0f : 0.0f;

        const bool fg0 = (la == 1.0f);
        const bool fg1 = (ign == 1.0f) || (ign == -2.0f);

        const float2 qi = __ldg((const float2*)rpn_iou + base);
        const float bval = (bi == ai) ? bm2 : bm1;

        if (fg0 || fg1) {
            const float4 rd0 = __ldg(pr);
            const float4 rd1 = __ldg(pr + 1);
            if (fg0) {
                const float4 g = sB[i1a];
                const float gw = g.z - g.x;
                const float gh = g.w - g.y;
                const float gcx = g.x + 0.5f * gw;
                const float gcy = g.y + 0.5f * gh;
                const float t0 = (gcx - acx) / aw;
                const float t1 = (gcy - acy) / ah;
                const float t2 = logf(gw / aw);
                const float t3 = logf(gh / ah);
                bb_s += sl1(rd0.x - t0) + sl1(rd0.y - t1) + sl1(rd0.z - t2) + sl1(rd0.w - t3);
                nfg += 1.0f;
                iou_s += fabsf(qi.x - am);
            }
            if (fg1) {
                const float4 g = sB[i2a];
                const float gw = g.z - g.x;
                const float gh = g.w - g.y;
                const float gcx = g.x + 0.5f * gw;
                const float gcy = g.y + 0.5f * gh;
                const float t0 = (gcx - acx) / aw;
                const float t1 = (gcy - acy) / ah;
                const float t2 = logf(gw / aw);
                const float t3 = logf(gh / ah);
                bb_s += sl1(rd1.x - t0) + sl1(rd1.y - t1) + sl1(rd1.z - t2) + sl1(rd1.w - t3);
                nfg += 1.0f;
                iou_s += fabsf(qi.y - bval);
            }
        }

        const int nl = ((la == 1.0f) ? 1 : 0) + ((ign == 1.0f) ? 1 : 0) - 1;
        if (nl >= 0) {
            const float2 sc = __ldg((const float2*)rpn_num_prob + base);
            const float mx = fmaxf(sc.x, sc.y);
            const float lse = mx + logf(expf(sc.x - mx) + expf(sc.y - mx));
            num_s += lse - ((nl == 0) ? sc.x : sc.y);
            nmask += 1.0f;
        }
    }

    // block reduction: warp shfl -> shared -> one double atomic per block per acc
    float vals[7] = {cls_s, npos, bb_s, nfg, iou_s, num_s, nmask};
    #pragma unroll
    for (int k = 0; k < 7; k++) {
        float v = vals[k];
        v += __shfl_down_sync(0xffffffffu, v, 16);
        v += __shfl_down_sync(0xffffffffu, v, 8);
        v += __shfl_down_sync(0xffffffffu, v, 4);
        v += __shfl_down_sync(0xffffffffu, v, 2);
        v += __shfl_down_sync(0xffffffffu, v, 1);
        vals[k] = v;
    }
    __shared__ float red[4][7];
    if (lane == 0) {
        #pragma unroll
        for (int k = 0; k < 7; k++) red[wid][k] = vals[k];
    }
    __syncthreads();
    if (tid < 7) {
        float s = red[0][tid] + red[1][tid] + red[2][tid] + red[3][tid];
        atomicAdd(&g_acc[tid], (double)s);
    }
}

__global__ void k_final(float* out) {
    if (threadIdx.x == 0) {
        const double npos = (g_acc[1] > 1.0) ? g_acc[1] : 1.0;
        const double nfg  = (g_acc[3] > 1.0) ? g_acc[3] : 1.0;
        const double nm   = (g_acc[6] > 1.0) ? g_acc[6] : 1.0;
        out[0] = (float)(g_acc[0] / npos);
        out[1] = (float)(2.0 * g_acc[2] / nfg);
        out[2] = (float)(2.0 * g_acc[4] / nfg);
        out[3] = (float)(g_acc[5] / nm);
    }
}

extern "C" void kernel_launch(void* const* d_in, const int* in_sizes, int n_in,
                              void* d_out, int out_size) {
    const float* pred_cls     = (const float*)d_in[0];
    const float* rpn_num_prob = (const float*)d_in[1];
    const float* pred_reg     = (const float*)d_in[2];
    const float* anchors      = (const float*)d_in[3];
    const float* rpn_iou      = (const float*)d_in[4];
    const float* boxes        = (const float*)d_in[5];
    // d_in[6] = im_info (unused; G and n recovered from sizes)

    const int A = in_sizes[3] / 4;
    const int n = in_sizes[0] / (2 * A);
    const int G = in_sizes[5] / (5 * n);

    k_zero<<<1, 256>>>();
    k_hist<<<(A + CHUNK - 1) / CHUNK, 256>>>(anchors, A);
    k_scan<<<1, 256>>>();
    k_scatter<<<(A + CHUNK - 1) / CHUNK, 256>>>(anchors, A);

    dim3 grid((A + 127) / 128, n);
    const size_t smem = (size_t)10 * G * sizeof(float);
    k_main<<<grid, 128, smem>>>(pred_cls, rpn_num_prob, pred_reg, anchors,
                                rpn_iou, boxes, A, G);
    k_final<<<1, 32>>>((float*)d_out);
}